// round 12
// baseline (speedup 1.0000x reference)
#include <cuda_runtime.h>
#include <cuda_bf16.h>
#include <math.h>

#define NN   256
#define CC   512
#define PP   256
#define KTOT 4608
#define STG_SZ 65536

typedef unsigned long long ull;

// ---------------- scratch ----------------
__device__ __align__(1024) __nv_bfloat16 g_qh[PP * NN * CC];
__device__ __align__(1024) __nv_bfloat16 g_ql[PP * NN * CC];
__device__ __align__(1024) __nv_bfloat16 g_kh[PP * NN * CC];
__device__ __align__(1024) __nv_bfloat16 g_kl[PP * NN * CC];
__device__ __align__(1024) __nv_bfloat16 g_vh[PP * NN * CC];
__device__ __align__(1024) __nv_bfloat16 g_vl[PP * NN * CC];
__device__ __align__(1024) float g_att[PP * NN * NN];
__device__ __align__(1024) __nv_bfloat16 g_atth[PP * NN * NN];
__device__ __align__(1024) __nv_bfloat16 g_attl[PP * NN * NN];
__device__ __align__(1024) float g_virt[PP * NN * CC];
__device__ __align__(1024) __nv_bfloat16 g_wh[4 * CC * KTOT];
__device__ __align__(1024) __nv_bfloat16 g_wl[4 * CC * KTOT];
__device__ __align__(1024) __nv_bfloat16 g_xh[NN * PP * CC];
__device__ __align__(1024) __nv_bfloat16 g_xl[NN * PP * CC];
__device__ __align__(1024) __nv_bfloat16 g_vbh[NN * PP * CC];
__device__ __align__(1024) __nv_bfloat16 g_vbl[NN * PP * CC];
__device__ float g_mu[NN];
__device__ float g_rs[NN];

// ---------------- sm_80-level PTX helpers ----------------
__device__ __forceinline__ unsigned smem_u32(const void* p) {
    unsigned a;
    asm("{ .reg .u64 t; cvta.to.shared.u64 t, %1; cvt.u32.u64 %0, t; }" : "=r"(a) : "l"(p));
    return a;
}
__device__ __forceinline__ void cp16(unsigned dst, const void* src) {
    asm volatile("cp.async.cg.shared.global [%0], [%1], 16;" :: "r"(dst), "l"(src) : "memory");
}
__device__ __forceinline__ void cp16z(unsigned dst, const void* src, unsigned sz) {
    asm volatile("cp.async.cg.shared.global [%0], [%1], 16, %2;" :: "r"(dst), "l"(src), "r"(sz) : "memory");
}
__device__ __forceinline__ void cp_commit() { asm volatile("cp.async.commit_group;" ::: "memory"); }
__device__ __forceinline__ void cp_wait1()  { asm volatile("cp.async.wait_group 1;" ::: "memory"); }
__device__ __forceinline__ void cp_wait0()  { asm volatile("cp.async.wait_group 0;" ::: "memory"); }
__device__ __forceinline__ void ldsm4(unsigned* r, unsigned a) {
    asm volatile("ldmatrix.sync.aligned.m8n8.x4.shared.b16 {%0,%1,%2,%3}, [%4];"
                 : "=r"(r[0]), "=r"(r[1]), "=r"(r[2]), "=r"(r[3]) : "r"(a));
}
__device__ __forceinline__ void ldsm4t(unsigned* r, unsigned a) {
    asm volatile("ldmatrix.sync.aligned.m8n8.x4.trans.shared.b16 {%0,%1,%2,%3}, [%4];"
                 : "=r"(r[0]), "=r"(r[1]), "=r"(r[2]), "=r"(r[3]) : "r"(a));
}
__device__ __forceinline__ void mma16816(float* d, const unsigned* a, const unsigned* b) {
    asm volatile(
        "mma.sync.aligned.m16n8k16.row.col.f32.bf16.bf16.f32 "
        "{%0,%1,%2,%3}, {%4,%5,%6,%7}, {%8,%9}, {%0,%1,%2,%3};"
        : "+f"(d[0]), "+f"(d[1]), "+f"(d[2]), "+f"(d[3])
        : "r"(a[0]), "r"(a[1]), "r"(a[2]), "r"(a[3]), "r"(b[0]), "r"(b[1]));
}

// ---------------- conversions ----------------
__global__ __launch_bounds__(256) void split_w_kernel(
    const float* __restrict__ Wq, const float* __restrict__ Wk,
    const float* __restrict__ Wv, const float* __restrict__ Wc)
{
    int idx = blockIdx.x * 256 + threadIdx.x;
    int conv = idx / (CC * KTOT);
    int r = idx - conv * (CC * KTOT);
    int co = r / KTOT, k = r - co * KTOT;
    int s = k >> 9, ci = k & 511;
    const float* W = (conv == 0) ? Wq : (conv == 1) ? Wk : (conv == 2) ? Wv : Wc;
    float v = W[(co * CC + ci) * 9 + s];
    __nv_bfloat16 h = __float2bfloat16(v);
    g_wh[idx] = h;
    g_wl[idx] = __float2bfloat16(v - __bfloat162float(h));
}

__global__ __launch_bounds__(256) void split_x_kernel(const float* __restrict__ x)
{
    __shared__ float ts[64][65];
    const int n = blockIdx.z, c0 = blockIdx.y * 64, p0 = blockIdx.x * 64;
    const int tid = threadIdx.x;
    for (int e = tid; e < 4096; e += 256) {
        int i = e >> 6, j = e & 63;
        ts[i][j] = x[(n * CC + c0 + i) * PP + p0 + j];
    }
    __syncthreads();
    for (int e = tid; e < 4096; e += 256) {
        int i = e >> 6, j = e & 63;
        float v = ts[j][i];
        __nv_bfloat16 h = __float2bfloat16(v);
        int o = (n * PP + p0 + i) * CC + c0 + j;
        g_xh[o] = h;
        g_xl[o] = __float2bfloat16(v - __bfloat162float(h));
    }
}

__global__ __launch_bounds__(256) void split_v_kernel(
    const float* __restrict__ gamma, const float* __restrict__ beta)
{
    const int pn = blockIdx.x;
    const int p = pn >> 8, n = pn & 255;
    const float mu = g_mu[n], rs = g_rs[n];
    for (int c = threadIdx.x; c < CC; c += 256) {
        float raw = g_virt[(p * NN + n) * CC + c];
        float ag = rs * gamma[c];
        float v = fmaxf(fmaf(raw, ag, beta[c] - mu * ag), 0.0f);
        __nv_bfloat16 h = __float2bfloat16(v);
        int o = (n * PP + p) * CC + c;
        g_vbh[o] = h;
        g_vbl[o] = __float2bfloat16(v - __bfloat162float(h));
    }
}

// ---------------- conv implicit GEMM, B resident per c-block ----------------
// CTA: M=128 co (mt) x N=256 p (all), one n. iters m=cb*9+sh (72).
// smem: A ring 3x32KB @0 ; B dbuf 2x64KB @98304 ; zero row 128B @229376.
#define A_OFF 0u
#define B_OFF 98304u
#define Z_OFF 229376u
#define CONV_SMEM 229504

__global__ __launch_bounds__(256, 1) void conv_mma_kernel(
    int conv_base, const float* __restrict__ x, float* __restrict__ out)
{
    extern __shared__ char dsm[];
    const unsigned sbase = smem_u32(dsm);
    const int tid = threadIdx.x, wid = tid >> 5, l = tid & 31;
    const int mt = blockIdx.x;
    const int n = blockIdx.y;
    const int conv_sel = conv_base + blockIdx.z;
    const int co0 = mt * 128;
    const __nv_bfloat16* bH = (conv_sel < 3) ? g_xh : g_vbh;
    const __nv_bfloat16* bL = (conv_sel < 3) ? g_xl : g_vbl;
    const int wm = wid >> 1, wn = wid & 1;   // warp tile: M32 x N128

    // zero row
    if (tid < 32) ((float*)(dsm + Z_OFF))[tid] = 0.0f;

    float d[2][16][4];
#pragma unroll
    for (int mi = 0; mi < 2; mi++)
#pragma unroll
        for (int nj = 0; nj < 16; nj++)
#pragma unroll
            for (int rg = 0; rg < 4; rg++) d[mi][nj][rg] = 0.0f;

    auto stageA = [&](int m) {
        const unsigned stg = sbase + A_OFF + (unsigned)(m % 3) * 32768u;
        const int cb = m / 9, sh = m - cb * 9;
        const int kbase = sh * 512 + cb * 64;
#pragma unroll
        for (int i = 0; i < 8; i++) {
            int idx = tid + 256 * i;
            int half = idx >> 10, r = (idx >> 3) & 127, seg = idx & 7;
            const __nv_bfloat16* src = (half ? g_wl : g_wh) +
                (size_t)(conv_sel * CC + co0 + r) * KTOT + kbase + seg * 8;
            cp16(stg + half * 16384 + r * 128 + ((seg ^ (r & 7)) << 4), src);
        }
    };
    auto stageB = [&](int cb, int s) {   // rows 32s..32s+31, both halves
        const unsigned bb = sbase + B_OFF + (unsigned)(cb & 1) * 65536u;
#pragma unroll
        for (int i = 0; i < 2; i++) {
            int idx = tid + 256 * i;            // 0..511
            int half = idx >> 8;
            int rem = idx & 255;
            int r = 32 * s + (rem >> 3), seg = rem & 7;
            const __nv_bfloat16* src = (half ? bL : bH) +
                (size_t)(n * PP + r) * CC + cb * 64 + seg * 8;
            cp16(bb + half * 32768 + r * 128 + ((seg ^ (r & 7)) << 4), src);
        }
    };

    // prologue: B(0) full, A(0), A(1)
    for (int s = 0; s < 8; s++) stageB(0, s);
    cp_commit();
    stageA(0); cp_commit();
    stageA(1); cp_commit();

    const unsigned zb = sbase + Z_OFF;
    const int kb = (l >> 3) & 1;

    for (int m = 0; m < 72; m++) {
        cp_wait1();
        __syncthreads();
        {   // issue next stage group (always exactly one commit per iter)
            if (m + 2 < 72) stageA(m + 2);
            int sh = m % 9, cb = m / 9;
            if (sh < 8 && cb + 1 < 8) stageB(cb + 1, sh);
            cp_commit();
        }
        const int cb = m / 9, sh = m - cb * 9;
        const int dh = sh / 3 - 1, dw = sh % 3 - 1;
        const unsigned astg = sbase + A_OFF + (unsigned)(m % 3) * 32768u;
        const unsigned bb = sbase + B_OFF + (unsigned)(cb & 1) * 65536u;

        // per-ng shifted row bases (shift applied at ldmatrix address)
        unsigned bA[8], hstep[8];
#pragma unroll
        for (int ng = 0; ng < 8; ng++) {
            int p = wn * 128 + ng * 16 + (l & 7) + ((l >> 4) << 3);
            int h = (p >> 3) & 7, w2 = p & 7;
            int ph = h + dh, pw = w2 + dw;
            bool ok = ((unsigned)ph < 8u) && ((unsigned)pw < 8u);
            int p2 = (p & ~63) + ph * 8 + pw;
            bA[ng] = ok ? (bb + (unsigned)(p2 * 128) + (unsigned)(p2 & 7)) : zb;
            hstep[ng] = ok ? 32768u : 0u;
        }

#pragma unroll
        for (int k16 = 0; k16 < 4; k16++) {
            unsigned a[2][2][4];
#pragma unroll
            for (int hf = 0; hf < 2; hf++)
#pragma unroll
                for (int mi = 0; mi < 2; mi++) {
                    int row = wm * 32 + mi * 16 + (l & 15);
                    ldsm4(a[hf][mi], astg + hf * 16384 + row * 128 +
                                     (((k16 * 2 + (l >> 4)) ^ (row & 7)) << 4));
                }
            const int seg = k16 * 2 + kb;
#pragma unroll
            for (int ng = 0; ng < 8; ng++) {
                unsigned sw = bA[ng] & 15u;
                unsigned base = (bA[ng] & ~15u) + (((unsigned)seg ^ sw) << 4);
                unsigned bh4[4], bl4[4];
                ldsm4(bh4, base);
                ldsm4(bl4, base + hstep[ng]);
#pragma unroll
                for (int mi = 0; mi < 2; mi++)
#pragma unroll
                    for (int jj = 0; jj < 2; jj++) {
                        float* dd = d[mi][2 * ng + jj];
                        mma16816(dd, a[0][mi], &bh4[2 * jj]);
                        mma16816(dd, a[0][mi], &bl4[2 * jj]);
                        mma16816(dd, a[1][mi], &bh4[2 * jj]);
                    }
            }
        }
    }

    cp_wait0();
    __syncthreads();
    float* ep = (float*)dsm;   // [co 128][p 256] pitch 257
#pragma unroll
    for (int mi = 0; mi < 2; mi++)
#pragma unroll
        for (int nj = 0; nj < 16; nj++)
#pragma unroll
            for (int rg = 0; rg < 4; rg++) {
                int row = wm * 32 + mi * 16 + (l >> 2) + (rg >> 1) * 8;
                int col = wn * 128 + nj * 8 + (l & 3) * 2 + (rg & 1);
                ep[row * 257 + col] = d[mi][nj][rg];
            }
    __syncthreads();
    if (conv_sel < 3) {
        __nv_bfloat16* dh2 = (conv_sel == 0) ? g_qh : (conv_sel == 1) ? g_kh : g_vh;
        __nv_bfloat16* dl2 = (conv_sel == 0) ? g_ql : (conv_sel == 1) ? g_kl : g_vl;
        for (int p = wid; p < 256; p += 8) {
            size_t o = ((size_t)p * NN + n) * CC + co0;
            for (int c = l; c < 128; c += 32) {
                float val = ep[c * 257 + p];
                __nv_bfloat16 h = __float2bfloat16(val);
                dh2[o + c] = h;
                dl2[o + c] = __float2bfloat16(val - __bfloat162float(h));
            }
        }
    } else {
        for (int r = wid; r < 128; r += 8) {
            size_t o = ((size_t)n * CC + co0 + r) * PP;
            for (int pc = l; pc < 256; pc += 32) out[o + pc] = x[o + pc] + ep[r * 257 + pc];
        }
    }
}

// ---------------- scores: S_p = (Q K^T)*scale on mma.sync ----------------
__global__ __launch_bounds__(256, 1) void scores_mma_kernel()
{
    extern __shared__ char dsm[];
    const unsigned sbase = smem_u32(dsm);
    const int tid = threadIdx.x, wid = tid >> 5, l = tid & 31;
    const int it = blockIdx.x & 1, jt = blockIdx.x >> 1;
    const int p = blockIdx.y;
    const int wm = wid >> 1, wn = wid & 1;
    const int i0 = it * 128, j0 = jt * 128;

    float d[2][8][4];
#pragma unroll
    for (int mi = 0; mi < 2; mi++)
#pragma unroll
        for (int nj = 0; nj < 8; nj++)
#pragma unroll
            for (int rg = 0; rg < 4; rg++) d[mi][nj][rg] = 0.0f;

    auto stage = [&](int c) {
        const unsigned stg = sbase + (unsigned)(c % 3) * STG_SZ;
        const int kbv = c * 64;
#pragma unroll
        for (int i = 0; i < 8; i++) {
            int idx = tid + 256 * i;
            int half = idx >> 10, r = (idx >> 3) & 127, seg = idx & 7;
            const __nv_bfloat16* src = (half ? g_ql : g_qh) + (size_t)(p * NN + i0 + r) * CC + kbv + seg * 8;
            cp16(stg + half * 16384 + r * 128 + ((seg ^ (r & 7)) << 4), src);
        }
#pragma unroll
        for (int i = 0; i < 8; i++) {
            int idx = tid + 256 * i;
            int half = idx >> 10, r = (idx >> 3) & 127, seg = idx & 7;
            const __nv_bfloat16* src = (half ? g_kl : g_kh) + (size_t)(p * NN + j0 + r) * CC + kbv + seg * 8;
            cp16(stg + 32768 + half * 16384 + r * 128 + ((seg ^ (r & 7)) << 4), src);
        }
        cp_commit();
    };

    stage(0); stage(1);
    for (int c = 0; c < 8; c++) {
        if (c + 1 >= 8) cp_wait0(); else cp_wait1();
        __syncthreads();
        if (c + 2 < 8) stage(c + 2);
        const unsigned stg = sbase + (unsigned)(c % 3) * STG_SZ;
#pragma unroll
        for (int k16 = 0; k16 < 4; k16++) {
            unsigned a[2][2][4];
#pragma unroll
            for (int hf = 0; hf < 2; hf++)
#pragma unroll
                for (int mi = 0; mi < 2; mi++) {
                    int row = wm * 32 + mi * 16 + (l & 15);
                    ldsm4(a[hf][mi], stg + hf * 16384 + row * 128 +
                                     (((k16 * 2 + (l >> 4)) ^ (row & 7)) << 4));
                }
            unsigned b[2][8][2];
#pragma unroll
            for (int hf = 0; hf < 2; hf++)
#pragma unroll
                for (int j = 0; j < 4; j++) {
                    int row = wn * 64 + j * 16 + (l & 7) + ((l >> 4) << 3);
                    int seg = k16 * 2 + ((l >> 3) & 1);
                    unsigned r4[4];
                    ldsm4(r4, stg + 32768 + hf * 16384 + row * 128 + ((seg ^ (row & 7)) << 4));
                    b[hf][2 * j][0] = r4[0]; b[hf][2 * j][1] = r4[1];
                    b[hf][2 * j + 1][0] = r4[2]; b[hf][2 * j + 1][1] = r4[3];
                }
#pragma unroll
            for (int mi = 0; mi < 2; mi++)
#pragma unroll
                for (int nj = 0; nj < 8; nj++) {
                    mma16816(d[mi][nj], a[0][mi], b[0][nj]);
                    mma16816(d[mi][nj], a[0][mi], b[1][nj]);
                    mma16816(d[mi][nj], a[1][mi], b[0][nj]);
                }
        }
    }
    cp_wait0();
    __syncthreads();
    float* ep = (float*)dsm;
    const float scale = rsqrtf((float)CC);
#pragma unroll
    for (int mi = 0; mi < 2; mi++)
#pragma unroll
        for (int nj = 0; nj < 8; nj++)
#pragma unroll
            for (int rg = 0; rg < 4; rg++) {
                int row = wm * 32 + mi * 16 + (l >> 2) + (rg >> 1) * 8;
                int col = wn * 64 + nj * 8 + (l & 3) * 2 + (rg & 1);
                ep[row * 129 + col] = d[mi][nj][rg] * scale;
            }
    __syncthreads();
    for (int r = wid; r < 128; r += 8) {
        float* dr = &g_att[((size_t)p * NN + i0 + r) * NN + j0];
        for (int c = l; c < 128; c += 32) dr[c] = ep[r * 129 + c];
    }
}

// ---------------- softmax (masked), emits bf16 hi/lo ----------------
__global__ __launch_bounds__(256) void softmax_kernel(const int* __restrict__ roi)
{
    __shared__ int rg[256];
    const int tid = threadIdx.x, l = tid & 31, wp = tid >> 5;
    rg[tid] = roi[tid];
    __syncthreads();
    const int row = blockIdx.x * 8 + wp;
    const int p = row >> 8, i = row & 255;
    const int gi = rg[i];
    const size_t ro = ((size_t)p * NN + i) * NN;
    float v[8];
#pragma unroll
    for (int jj = 0; jj < 8; jj++) {
        int j = jj * 32 + l;
        float s = g_att[ro + j];
        v[jj] = (rg[j] == gi) ? s : -1e30f;
    }
    float m = v[0];
#pragma unroll
    for (int jj = 1; jj < 8; jj++) m = fmaxf(m, v[jj]);
#pragma unroll
    for (int off = 16; off; off >>= 1) m = fmaxf(m, __shfl_xor_sync(0xffffffffu, m, off));
    float e[8]; float sum = 0.0f;
#pragma unroll
    for (int jj = 0; jj < 8; jj++) { e[jj] = expf(v[jj] - m); sum += e[jj]; }
#pragma unroll
    for (int off = 16; off; off >>= 1) sum += __shfl_xor_sync(0xffffffffu, sum, off);
    const float inv = 1.0f / sum;
#pragma unroll
    for (int jj = 0; jj < 8; jj++) {
        float a = e[jj] * inv;
        __nv_bfloat16 h = __float2bfloat16(a);
        g_atth[ro + jj * 32 + l] = h;
        g_attl[ro + jj * 32 + l] = __float2bfloat16(a - __bfloat162float(h));
    }
}

// ---------------- virt = att · V on mma.sync (B via ldmatrix.trans) --------
__global__ __launch_bounds__(256, 1) void virt_mma_kernel()
{
    extern __shared__ char dsm[];
    const unsigned sbase = smem_u32(dsm);
    const int tid = threadIdx.x, wid = tid >> 5, l = tid & 31;
    const int it = blockIdx.x & 1, ct = blockIdx.x >> 1;
    const int p = blockIdx.y;
    const int wm = wid >> 1, wn = wid & 1;
    const int i0 = it * 128, c0 = ct * 128;

    float d[2][8][4];
#pragma unroll
    for (int mi = 0; mi < 2; mi++)
#pragma unroll
        for (int nj = 0; nj < 8; nj++)
#pragma unroll
            for (int rg = 0; rg < 4; rg++) d[mi][nj][rg] = 0.0f;

    auto stage = [&](int c) {
        const unsigned stg = sbase + (unsigned)(c % 3) * STG_SZ;
        const int j0 = c * 64;
#pragma unroll
        for (int i = 0; i < 8; i++) {
            int idx = tid + 256 * i;
            int half = idx >> 10, r = (idx >> 3) & 127, seg = idx & 7;
            const __nv_bfloat16* src = (half ? g_attl : g_atth) + (size_t)(p * NN + i0 + r) * NN + j0 + seg * 8;
            cp16(stg + half * 16384 + r * 128 + ((seg ^ (r & 7)) << 4), src);
        }
#pragma unroll
        for (int i = 0; i < 8; i++) {
            int idx = tid + 256 * i;
            int half = idx >> 10, rem = idx & 1023;
            int r = rem >> 4, seg = rem & 15;
            const __nv_bfloat16* src = (half ? g_vl : g_vh) + (size_t)(p * NN + j0 + r) * CC + c0 + seg * 8;
            cp16(stg + 32768 + half * 16384 + r * 256 + ((seg ^ ((r & 7) << 1)) << 4), src);
        }
        cp_commit();
    };

    stage(0); stage(1);
    for (int c = 0; c < 4; c++) {
        if (c + 1 >= 4) cp_wait0(); else cp_wait1();
        __syncthreads();
        if (c + 2 < 4) stage(c + 2);
        const unsigned stg = sbase + (unsigned)(c % 3) * STG_SZ;
#pragma unroll
        for (int k16 = 0; k16 < 4; k16++) {
            unsigned a[2][2][4];
#pragma unroll
            for (int hf = 0; hf < 2; hf++)
#pragma unroll
                for (int mi = 0; mi < 2; mi++) {
                    int row = wm * 32 + mi * 16 + (l & 15);
                    ldsm4(a[hf][mi], stg + hf * 16384 + row * 128 +
                                     (((k16 * 2 + (l >> 4)) ^ (row & 7)) << 4));
                }
            unsigned b[2][8][2];
#pragma unroll
            for (int hf = 0; hf < 2; hf++)
#pragma unroll
                for (int cg = 0; cg < 4; cg++) {
                    int tileid = l >> 3;
                    int jr = (l & 7) + (tileid & 1) * 8;
                    int row = k16 * 16 + jr;
                    int seg = wn * 8 + cg * 2 + (tileid >> 1);
                    unsigned r4[4];
                    ldsm4t(r4, stg + 32768 + hf * 16384 + row * 256 +
                               ((seg ^ ((row & 7) << 1)) << 4));
                    b[hf][2 * cg][0] = r4[0]; b[hf][2 * cg][1] = r4[1];
                    b[hf][2 * cg + 1][0] = r4[2]; b[hf][2 * cg + 1][1] = r4[3];
                }
#pragma unroll
            for (int mi = 0; mi < 2; mi++)
#pragma unroll
                for (int nj = 0; nj < 8; nj++) {
                    mma16816(d[mi][nj], a[0][mi], b[0][nj]);
                    mma16816(d[mi][nj], a[0][mi], b[1][nj]);
                    mma16816(d[mi][nj], a[1][mi], b[0][nj]);
                }
        }
    }
    cp_wait0();
    __syncthreads();
    float* ep = (float*)dsm;
#pragma unroll
    for (int mi = 0; mi < 2; mi++)
#pragma unroll
        for (int nj = 0; nj < 8; nj++)
#pragma unroll
            for (int rg = 0; rg < 4; rg++) {
                int row = wm * 32 + mi * 16 + (l >> 2) + (rg >> 1) * 8;
                int col = wn * 64 + nj * 8 + (l & 3) * 2 + (rg & 1);
                ep[row * 129 + col] = d[mi][nj][rg];
            }
    __syncthreads();
    for (int r = wid; r < 128; r += 8) {
        float* dr = &g_virt[((size_t)p * NN + i0 + r) * CC + c0];
        for (int c = l; c < 128; c += 32) dr[c] = ep[r * 129 + c];
    }
}

// ---------------- GN stats ----------------
__global__ __launch_bounds__(256) void stats_kernel()
{
    __shared__ float r1[256];
    __shared__ float r2[256];
    const int n = blockIdx.x, tid = threadIdx.x;
    float s = 0.0f, s2 = 0.0f;
    for (int e = tid; e < PP * CC; e += 256) {
        int p = e >> 9, c = e & 511;
        float v = g_virt[(p * NN + n) * CC + c];
        s += v; s2 += v * v;
    }
    r1[tid] = s; r2[tid] = s2;
    __syncthreads();
    for (int off = 128; off; off >>= 1) {
        if (tid < off) { r1[tid] += r1[tid + off]; r2[tid] += r2[tid + off]; }
        __syncthreads();
    }
    if (tid == 0) {
        const float invN = 1.0f / (float)(PP * CC);
        float mu = r1[0] * invN;
        float var = r2[0] * invN - mu * mu;
        g_mu[n] = mu;
        g_rs[n] = rsqrtf(var + 1e-5f);
    }
}

// ---------------- host ----------------
extern "C" void kernel_launch(void* const* d_in, const int* in_sizes, int n_in,
                              void* d_out, int out_size)
{
    const float* x     = (const float*)d_in[0];
    const int*   roi   = (const int*)d_in[1];
    const float* Wq    = (const float*)d_in[2];
    const float* Wk    = (const float*)d_in[3];
    const float* Wv    = (const float*)d_in[4];
    const float* Wc    = (const float*)d_in[5];
    const float* gamma = (const float*)d_in[6];
    const float* beta  = (const float*)d_in[7];
    float* out = (float*)d_out;

    cudaFuncSetAttribute(conv_mma_kernel,   cudaFuncAttributeMaxDynamicSharedMemorySize, CONV_SMEM);
    cudaFuncSetAttribute(scores_mma_kernel, cudaFuncAttributeMaxDynamicSharedMemorySize, 3 * STG_SZ);
    cudaFuncSetAttribute(virt_mma_kernel,   cudaFuncAttributeMaxDynamicSharedMemorySize, 3 * STG_SZ);

    split_w_kernel<<<36864, 256>>>(Wq, Wk, Wv, Wc);
    split_x_kernel<<<dim3(4, 8, 256), 256>>>(x);
    conv_mma_kernel<<<dim3(4, 256, 3), 256, CONV_SMEM>>>(0, x, out);    // q,k,v
    scores_mma_kernel<<<dim3(4, 256), 256, 3 * STG_SZ>>>();
    softmax_kernel<<<8192, 256>>>(roi);
    virt_mma_kernel<<<dim3(8, 256), 256, 3 * STG_SZ>>>();
    stats_kernel<<<256, 256>>>();
    split_v_kernel<<<65536, 256>>>(gamma, beta);
    conv_mma_kernel<<<dim3(4, 256, 1), 256, CONV_SMEM>>>(3, x, out);    // out conv
}

// round 15
// speedup vs baseline: 1.5867x; 1.5867x over previous
#include <cuda_runtime.h>
#include <cuda_bf16.h>
#include <math.h>

#define NN 256
#define CC 512
#define PP 256
#define NTILE 16384
#define STG_SZ 65536

typedef unsigned long long ull;

// ---------------- scratch ----------------
__device__ __align__(1024) __nv_bfloat16 g_qh[PP * NN * CC];
__device__ __align__(1024) __nv_bfloat16 g_ql[PP * NN * CC];
__device__ __align__(1024) __nv_bfloat16 g_kh[PP * NN * CC];
__device__ __align__(1024) __nv_bfloat16 g_kl[PP * NN * CC];
__device__ __align__(1024) __nv_bfloat16 g_vh[PP * NN * CC];
__device__ __align__(1024) __nv_bfloat16 g_vl[PP * NN * CC];
__device__ __align__(1024) float g_att[PP * NN * NN];
__device__ __align__(1024) __nv_bfloat16 g_atth[PP * NN * NN];
__device__ __align__(1024) __nv_bfloat16 g_attl[PP * NN * NN];
__device__ __align__(1024) float g_virt[PP * NN * CC];
__device__ float g_mu[NN];
__device__ float g_rs[NN];
__device__ __align__(1024) __nv_bfloat16 g_uh[16 * 2048 * 512];
__device__ __align__(1024) __nv_bfloat16 g_ul[16 * 2048 * 512];
__device__ __align__(1024) __nv_bfloat16 g_wvh[(size_t)16 * NTILE * 512];
__device__ __align__(1024) __nv_bfloat16 g_wvl[(size_t)16 * NTILE * 512];
__device__ __align__(1024) float g_m[(size_t)16 * NTILE * 1536];

// ---------------- helpers ----------------
__device__ __forceinline__ unsigned smem_u32(const void* p) {
    unsigned a;
    asm("{ .reg .u64 t; cvta.to.shared.u64 t, %1; cvt.u32.u64 %0, t; }" : "=r"(a) : "l"(p));
    return a;
}
__device__ __forceinline__ void cp16(unsigned dst, const void* src) {
    asm volatile("cp.async.cg.shared.global [%0], [%1], 16;" :: "r"(dst), "l"(src) : "memory");
}
__device__ __forceinline__ void cp_commit() { asm volatile("cp.async.commit_group;" ::: "memory"); }
__device__ __forceinline__ void cp_wait1()  { asm volatile("cp.async.wait_group 1;" ::: "memory"); }
__device__ __forceinline__ void cp_wait0()  { asm volatile("cp.async.wait_group 0;" ::: "memory"); }
__device__ __forceinline__ void ldsm4(unsigned* r, unsigned a) {
    asm volatile("ldmatrix.sync.aligned.m8n8.x4.shared.b16 {%0,%1,%2,%3}, [%4];"
                 : "=r"(r[0]), "=r"(r[1]), "=r"(r[2]), "=r"(r[3]) : "r"(a));
}
__device__ __forceinline__ void ldsm4t(unsigned* r, unsigned a) {
    asm volatile("ldmatrix.sync.aligned.m8n8.x4.trans.shared.b16 {%0,%1,%2,%3}, [%4];"
                 : "=r"(r[0]), "=r"(r[1]), "=r"(r[2]), "=r"(r[3]) : "r"(a));
}
__device__ __forceinline__ void mma16816(float* d, const unsigned* a, const unsigned* b) {
    asm volatile(
        "mma.sync.aligned.m16n8k16.row.col.f32.bf16.bf16.f32 "
        "{%0,%1,%2,%3}, {%4,%5,%6,%7}, {%8,%9}, {%0,%1,%2,%3};"
        : "+f"(d[0]), "+f"(d[1]), "+f"(d[2]), "+f"(d[3])
        : "r"(a[0]), "r"(a[1]), "r"(a[2]), "r"(a[3]), "r"(b[0]), "r"(b[1]));
}
__device__ __forceinline__ void bfsplit(float v, __nv_bfloat16& h, __nv_bfloat16& lo) {
    h = __float2bfloat16(v);
    lo = __float2bfloat16(v - __bfloat162float(h));
}

// ---------------- U = G g G^T for all 4 convs, bf16 hi/lo -----------------
__global__ __launch_bounds__(256) void wino_u_kernel(
    const float* __restrict__ Wq, const float* __restrict__ Wk,
    const float* __restrict__ Wv, const float* __restrict__ Wc)
{
    int idx = blockIdx.x * 256 + threadIdx.x;      // < 4*512*512
    int conv = idx >> 18, rem = idx & 262143;
    int co = rem >> 9, ci = rem & 511;
    const float* W = (conv == 0) ? Wq : (conv == 1) ? Wk : (conv == 2) ? Wv : Wc;
    const float* g = W + ((size_t)co * 512 + ci) * 9;
    float g3[3][3];
#pragma unroll
    for (int s = 0; s < 9; s++) g3[s / 3][s % 3] = g[s];
    float u1[4][3];
#pragma unroll
    for (int j = 0; j < 3; j++) {
        u1[0][j] = g3[0][j];
        u1[1][j] = 0.5f * (g3[0][j] + g3[1][j] + g3[2][j]);
        u1[2][j] = 0.5f * (g3[0][j] - g3[1][j] + g3[2][j]);
        u1[3][j] = g3[2][j];
    }
#pragma unroll
    for (int i = 0; i < 4; i++) {
        float a0 = u1[i][0], a1 = u1[i][1], a2 = u1[i][2];
        float uu[4] = { a0, 0.5f * (a0 + a1 + a2), 0.5f * (a0 - a1 + a2), a2 };
#pragma unroll
        for (int j = 0; j < 4; j++) {
            size_t off = ((size_t)(i * 4 + j) * 2048 + conv * 512 + co) * 512 + ci;
            bfsplit(uu[j], g_uh[off], g_ul[off]);
        }
    }
}

// ---------------- V = B^T d B ; mode0: x, mode1: GN(virt)+relu ------------
__global__ __launch_bounds__(512) void wino_v_kernel(
    int mode, const float* __restrict__ x,
    const float* __restrict__ gamma, const float* __restrict__ beta)
{
    extern __shared__ char vsm[];
    float* xs = (float*)vsm;                             // 512*65 f32
    __nv_bfloat16* vb = (__nv_bfloat16*)(vsm + 133120);  // 32768 bf16
    const int n = blockIdx.x >> 2, t = blockIdx.x & 3;
    const int tid = threadIdx.x;

    if (mode == 0) {
        for (int i = 0; i < 64; i++) {
            int idx = tid + i * 512;
            int c = idx >> 6, p = idx & 63;
            xs[c * 65 + p] = x[((size_t)n * 512 + c) * 256 + t * 64 + p];
        }
    } else {
        const float mu = g_mu[n], rs = g_rs[n];
        const int c = tid;
        const float ag = rs * gamma[c], bb = beta[c] - mu * ag;
        for (int p = 0; p < 64; p++) {
            float raw = g_virt[((size_t)(t * 64 + p) * 256 + n) * 512 + c];
            xs[c * 65 + p] = fmaxf(fmaf(raw, ag, bb), 0.0f);
        }
    }
    __syncthreads();
    const int c = tid;
    for (int tb = 0; tb < 8; tb++) {
#pragma unroll
        for (int t2 = 0; t2 < 2; t2++) {
            int tt = tb * 2 + t2;
            int ty = tt >> 2, tx = tt & 3;
            float d4[4][4];
#pragma unroll
            for (int ii = 0; ii < 4; ii++)
#pragma unroll
                for (int jj = 0; jj < 4; jj++) {
                    int ry = 2 * ty - 1 + ii, rx = 2 * tx - 1 + jj;
                    d4[ii][jj] = ((unsigned)ry < 8u && (unsigned)rx < 8u)
                                 ? xs[c * 65 + ry * 8 + rx] : 0.0f;
                }
            float t4[4][4];
#pragma unroll
            for (int j = 0; j < 4; j++) {
                t4[0][j] = d4[0][j] - d4[2][j];
                t4[1][j] = d4[1][j] + d4[2][j];
                t4[2][j] = d4[2][j] - d4[1][j];
                t4[3][j] = d4[1][j] - d4[3][j];
            }
#pragma unroll
            for (int i2 = 0; i2 < 4; i2++) {
                float vv[4];
                vv[0] = t4[i2][0] - t4[i2][2];
                vv[1] = t4[i2][1] + t4[i2][2];
                vv[2] = t4[i2][2] - t4[i2][1];
                vv[3] = t4[i2][1] - t4[i2][3];
#pragma unroll
                for (int j2 = 0; j2 < 4; j2++) {
                    int pt = i2 * 4 + j2;
                    __nv_bfloat16 h, lo; bfsplit(vv[j2], h, lo);
                    vb[((t2 * 16 + pt) * 2 + 0) * 512 + c] = h;
                    vb[((t2 * 16 + pt) * 2 + 1) * 512 + c] = lo;
                }
            }
        }
        __syncthreads();
        for (int i = 0; i < 8; i++) {
            int q = tid + i * 512;               // 0..4095
            int c0 = (q & 63) * 8;
            int rest = q >> 6;                   // t2*32 + pt*2 + half
            int half = rest & 1, pt = (rest >> 1) & 15, t2 = rest >> 5;
            int tg = n * 64 + t * 16 + tb * 2 + t2;
            __nv_bfloat16* dst = half ? g_wvl : g_wvh;
            *(float4*)&dst[((size_t)pt * NTILE + tg) * 512 + c0] =
                *(const float4*)&vb[((t2 * 16 + pt) * 2 + half) * 512 + c0];
        }
        __syncthreads();
    }
}

// ------------- batched point GEMM: M[pt] = U[pt] * V[pt]^T ----------------
// grid (64, mtot/128, 16).  CTA M128 x N256, K=512 in 8 chunks of 64.
__global__ __launch_bounds__(256, 1) void wino_gemm_kernel(int a_row0, int mtot)
{
    extern __shared__ char dsm[];
    const unsigned sb = smem_u32(dsm);
    const int tid = threadIdx.x, wid = tid >> 5, l = tid & 31;
    const int tile0 = blockIdx.x * 256, row0 = blockIdx.y * 128, pt = blockIdx.z;
    const int wm = wid >> 1, wn = wid & 1;

    float d[2][16][4];
#pragma unroll
    for (int mi = 0; mi < 2; mi++)
#pragma unroll
        for (int nj = 0; nj < 16; nj++)
#pragma unroll
            for (int rg = 0; rg < 4; rg++) d[mi][nj][rg] = 0.0f;

    auto stage = [&](int c) {
        const unsigned ast = sb + (unsigned)(c & 1) * 32768u;
        const unsigned bst = sb + 65536u + (unsigned)(c & 1) * 65536u;
        const int kb = c * 64;
#pragma unroll
        for (int i = 0; i < 8; i++) {
            int idx = tid + 256 * i;
            int half = idx >> 10, r = (idx >> 3) & 127, seg = idx & 7;
            const __nv_bfloat16* src = (half ? g_ul : g_uh) +
                ((size_t)pt * 2048 + a_row0 + row0 + r) * 512 + kb + seg * 8;
            cp16(ast + half * 16384 + r * 128 + ((seg ^ (r & 7)) << 4), src);
        }
#pragma unroll
        for (int i = 0; i < 16; i++) {
            int idx = tid + 256 * i;
            int half = idx >> 11, rem = idx & 2047;
            int r = rem >> 3, seg = rem & 7;
            const __nv_bfloat16* src = (half ? g_wvl : g_wvh) +
                ((size_t)pt * NTILE + tile0 + r) * 512 + kb + seg * 8;
            cp16(bst + half * 32768 + r * 128 + ((seg ^ (r & 7)) << 4), src);
        }
        cp_commit();
    };

    stage(0); stage(1);
    for (int c = 0; c < 8; c++) {
        if (c + 1 >= 8) cp_wait0(); else cp_wait1();
        __syncthreads();
        const unsigned ast = sb + (unsigned)(c & 1) * 32768u;
        const unsigned bst = sb + 65536u + (unsigned)(c & 1) * 65536u;
#pragma unroll
        for (int k16 = 0; k16 < 4; k16++) {
            unsigned a[2][2][4];
#pragma unroll
            for (int hf = 0; hf < 2; hf++)
#pragma unroll
                for (int mi = 0; mi < 2; mi++) {
                    int row = wm * 32 + mi * 16 + (l & 15);
                    ldsm4(a[hf][mi], ast + hf * 16384 + row * 128 +
                                     (((k16 * 2 + (l >> 4)) ^ (row & 7)) << 4));
                }
            const int seg = k16 * 2 + ((l >> 3) & 1);
#pragma unroll
            for (int ng = 0; ng < 8; ng++) {
                int row = wn * 128 + ng * 16 + (l & 7) + ((l >> 4) << 3);
                unsigned addr = bst + row * 128 + ((seg ^ (row & 7)) << 4);
                unsigned bh4[4], bl4[4];
                ldsm4(bh4, addr);
                ldsm4(bl4, addr + 32768u);
#pragma unroll
                for (int mi = 0; mi < 2; mi++)
#pragma unroll
                    for (int jj = 0; jj < 2; jj++) {
                        float* dd = d[mi][2 * ng + jj];
                        mma16816(dd, a[0][mi], &bh4[2 * jj]);
                        mma16816(dd, a[0][mi], &bl4[2 * jj]);
                        mma16816(dd, a[1][mi], &bh4[2 * jj]);
                    }
            }
        }
        __syncthreads();
        if (c + 2 < 8) stage(c + 2);
    }

    cp_wait0();
    __syncthreads();
    float* ep = (float*)dsm;   // [m 128][tile 256] pitch 257
#pragma unroll
    for (int mi = 0; mi < 2; mi++)
#pragma unroll
        for (int nj = 0; nj < 16; nj++)
#pragma unroll
            for (int rg = 0; rg < 4; rg++) {
                int row = wm * 32 + mi * 16 + (l >> 2) + (rg >> 1) * 8;
                int col = wn * 128 + nj * 8 + (l & 3) * 2 + (rg & 1);
                ep[row * 257 + col] = d[mi][nj][rg];
            }
    __syncthreads();
    for (int col = wid; col < 256; col += 8) {
        size_t base = ((size_t)pt * NTILE + tile0 + col) * mtot + row0;
        for (int r = l; r < 128; r += 32) g_m[base + r] = ep[r * 257 + col];
    }
}

// ------------- inverse Y = A^T M A -> q/k/v bf16 hi/lo --------------------
__global__ __launch_bounds__(512) void wino_inv_qkv_kernel()
{
    __shared__ __nv_bfloat16 vb[12288];
    const int tg = blockIdx.x;
    const int co = threadIdx.x;
    const int n = tg >> 6, t = (tg >> 4) & 3, ty = (tg >> 2) & 3, tx = tg & 3;
    for (int conv = 0; conv < 3; conv++) {
        float m[16];
#pragma unroll
        for (int pt = 0; pt < 16; pt++)
            m[pt] = g_m[((size_t)pt * NTILE + tg) * 1536 + conv * 512 + co];
        float r0[4], r1[4];
#pragma unroll
        for (int j = 0; j < 4; j++) {
            r0[j] = m[j] + m[4 + j] + m[8 + j];
            r1[j] = m[4 + j] - m[8 + j] - m[12 + j];
        }
        float y[2][2];
        y[0][0] = r0[0] + r0[1] + r0[2]; y[0][1] = r0[1] - r0[2] - r0[3];
        y[1][0] = r1[0] + r1[1] + r1[2]; y[1][1] = r1[1] - r1[2] - r1[3];
#pragma unroll
        for (int a = 0; a < 2; a++)
#pragma unroll
            for (int b = 0; b < 2; b++) {
                __nv_bfloat16 h, lo; bfsplit(y[a][b], h, lo);
                vb[(((conv * 2 + a) * 2 + b) * 2 + 0) * 512 + co] = h;
                vb[(((conv * 2 + a) * 2 + b) * 2 + 1) * 512 + co] = lo;
            }
    }
    __syncthreads();
#pragma unroll
    for (int i = 0; i < 3; i++) {
        int q = threadIdx.x + i * 512;
        int c0 = (q & 63) * 8;
        int rest = q >> 6;        // conv*8 + a*4 + b*2 + half
        int half = rest & 1, b = (rest >> 1) & 1, a = (rest >> 2) & 1, conv = rest >> 3;
        int p = t * 64 + (2 * ty + a) * 8 + 2 * tx + b;
        __nv_bfloat16* dst =
            (conv == 0) ? (half ? g_ql : g_qh) :
            (conv == 1) ? (half ? g_kl : g_kh) : (half ? g_vl : g_vh);
        *(float4*)&dst[((size_t)p * 256 + n) * 512 + c0] =
            *(const float4*)&vb[(((conv * 2 + a) * 2 + b) * 2 + half) * 512 + c0];
    }
}

// ------------- inverse -> out (residual fused) ----------------------------
__global__ __launch_bounds__(512) void wino_inv_out_kernel(
    const float* __restrict__ x, float* __restrict__ out)
{
    extern __shared__ float ep2[];   // [64 p][512 co]
    const int n = blockIdx.x >> 2, t = blockIdx.x & 3;
    const int co = threadIdx.x;
    for (int tt = 0; tt < 16; tt++) {
        int ty = tt >> 2, tx = tt & 3;
        int tg = n * 64 + t * 16 + tt;
        float m[16];
#pragma unroll
        for (int pt = 0; pt < 16; pt++)
            m[pt] = g_m[((size_t)pt * NTILE + tg) * 512 + co];
        float r0[4], r1[4];
#pragma unroll
        for (int j = 0; j < 4; j++) {
            r0[j] = m[j] + m[4 + j] + m[8 + j];
            r1[j] = m[4 + j] - m[8 + j] - m[12 + j];
        }
        ep2[((2 * ty + 0) * 8 + 2 * tx + 0) * 512 + co] = r0[0] + r0[1] + r0[2];
        ep2[((2 * ty + 0) * 8 + 2 * tx + 1) * 512 + co] = r0[1] - r0[2] - r0[3];
        ep2[((2 * ty + 1) * 8 + 2 * tx + 0) * 512 + co] = r1[0] + r1[1] + r1[2];
        ep2[((2 * ty + 1) * 8 + 2 * tx + 1) * 512 + co] = r1[1] - r1[2] - r1[3];
    }
    __syncthreads();
    size_t base = ((size_t)n * 512 + co) * 256 + t * 64;
    for (int p = 0; p < 64; p++)
        out[base + p] = x[base + p] + ep2[p * 512 + co];
}

// ---------------- attention (proven R11/R12 kernels) ----------------------
__global__ __launch_bounds__(256, 1) void scores_mma_kernel()
{
    extern __shared__ char dsm[];
    const unsigned sbase = smem_u32(dsm);
    const int tid = threadIdx.x, wid = tid >> 5, l = tid & 31;
    const int it = blockIdx.x & 1, jt = blockIdx.x >> 1;
    const int p = blockIdx.y;
    const int wm = wid >> 1, wn = wid & 1;
    const int i0 = it * 128, j0 = jt * 128;

    float d[2][8][4];
#pragma unroll
    for (int mi = 0; mi < 2; mi++)
#pragma unroll
        for (int nj = 0; nj < 8; nj++)
#pragma unroll
            for (int rg = 0; rg < 4; rg++) d[mi][nj][rg] = 0.0f;

    auto stage = [&](int c) {
        const unsigned stg = sbase + (unsigned)(c % 3) * STG_SZ;
        const int kbv = c * 64;
#pragma unroll
        for (int i = 0; i < 8; i++) {
            int idx = tid + 256 * i;
            int half = idx >> 10, r = (idx >> 3) & 127, seg = idx & 7;
            const __nv_bfloat16* src = (half ? g_ql : g_qh) + (size_t)(p * NN + i0 + r) * CC + kbv + seg * 8;
            cp16(stg + half * 16384 + r * 128 + ((seg ^ (r & 7)) << 4), src);
        }
#pragma unroll
        for (int i = 0; i < 8; i++) {
            int idx = tid + 256 * i;
            int half = idx >> 10, r = (idx >> 3) & 127, seg = idx & 7;
            const __nv_bfloat16* src = (half ? g_kl : g_kh) + (size_t)(p * NN + j0 + r) * CC + kbv + seg * 8;
            cp16(stg + 32768 + half * 16384 + r * 128 + ((seg ^ (r & 7)) << 4), src);
        }
        cp_commit();
    };

    stage(0); stage(1);
    for (int c = 0; c < 8; c++) {
        if (c + 1 >= 8) cp_wait0(); else cp_wait1();
        __syncthreads();
        if (c + 2 < 8) stage(c + 2);
        const unsigned stg = sbase + (unsigned)(c % 3) * STG_SZ;
#pragma unroll
        for (int k16 = 0; k16 < 4; k16++) {
            unsigned a[2][2][4];
#pragma unroll
            for (int hf = 0; hf < 2; hf++)
#pragma unroll
                for (int mi = 0; mi < 2; mi++) {
                    int row = wm * 32 + mi * 16 + (l & 15);
                    ldsm4(a[hf][mi], stg + hf * 16384 + row * 128 +
                                     (((k16 * 2 + (l >> 4)) ^ (row & 7)) << 4));
                }
            unsigned b[2][8][2];
#pragma unroll
            for (int hf = 0; hf < 2; hf++)
#pragma unroll
                for (int j = 0; j < 4; j++) {
                    int row = wn * 64 + j * 16 + (l & 7) + ((l >> 4) << 3);
                    int seg = k16 * 2 + ((l >> 3) & 1);
                    unsigned r4[4];
                    ldsm4(r4, stg + 32768 + hf * 16384 + row * 128 + ((seg ^ (row & 7)) << 4));
                    b[hf][2 * j][0] = r4[0]; b[hf][2 * j][1] = r4[1];
                    b[hf][2 * j + 1][0] = r4[2]; b[hf][2 * j + 1][1] = r4[3];
                }
#pragma unroll
            for (int mi = 0; mi < 2; mi++)
#pragma unroll
                for (int nj = 0; nj < 8; nj++) {
                    mma16816(d[mi][nj], a[0][mi], b[0][nj]);
                    mma16816(d[mi][nj], a[0][mi], b[1][nj]);
                    mma16816(d[mi][nj], a[1][mi], b[0][nj]);
                }
        }
    }
    cp_wait0();
    __syncthreads();
    float* ep = (float*)dsm;
    const float scale = rsqrtf((float)CC);
#pragma unroll
    for (int mi = 0; mi < 2; mi++)
#pragma unroll
        for (int nj = 0; nj < 8; nj++)
#pragma unroll
            for (int rg = 0; rg < 4; rg++) {
                int row = wm * 32 + mi * 16 + (l >> 2) + (rg >> 1) * 8;
                int col = wn * 64 + nj * 8 + (l & 3) * 2 + (rg & 1);
                ep[row * 129 + col] = d[mi][nj][rg] * scale;
            }
    __syncthreads();
    for (int r = wid; r < 128; r += 8) {
        float* dr = &g_att[((size_t)p * NN + i0 + r) * NN + j0];
        for (int c = l; c < 128; c += 32) dr[c] = ep[r * 129 + c];
    }
}

__global__ __launch_bounds__(256) void softmax_kernel(const int* __restrict__ roi)
{
    __shared__ int rg[256];
    const int tid = threadIdx.x, l = tid & 31, wp = tid >> 5;
    rg[tid] = roi[tid];
    __syncthreads();
    const int row = blockIdx.x * 8 + wp;
    const int p = row >> 8, i = row & 255;
    const int gi = rg[i];
    const size_t ro = ((size_t)p * NN + i) * NN;
    float v[8];
#pragma unroll
    for (int jj = 0; jj < 8; jj++) {
        int j = jj * 32 + l;
        float s = g_att[ro + j];
        v[jj] = (rg[j] == gi) ? s : -1e30f;
    }
    float m = v[0];
#pragma unroll
    for (int jj = 1; jj < 8; jj++) m = fmaxf(m, v[jj]);
#pragma unroll
    for (int off = 16; off; off >>= 1) m = fmaxf(m, __shfl_xor_sync(0xffffffffu, m, off));
    float e[8]; float sum = 0.0f;
#pragma unroll
    for (int jj = 0; jj < 8; jj++) { e[jj] = expf(v[jj] - m); sum += e[jj]; }
#pragma unroll
    for (int off = 16; off; off >>= 1) sum += __shfl_xor_sync(0xffffffffu, sum, off);
    const float inv = 1.0f / sum;
#pragma unroll
    for (int jj = 0; jj < 8; jj++) {
        float a = e[jj] * inv;
        __nv_bfloat16 h, lo; bfsplit(a, h, lo);
        g_atth[ro + jj * 32 + l] = h;
        g_attl[ro + jj * 32 + l] = lo;
    }
}

__global__ __launch_bounds__(256, 1) void virt_mma_kernel()
{
    extern __shared__ char dsm[];
    const unsigned sbase = smem_u32(dsm);
    const int tid = threadIdx.x, wid = tid >> 5, l = tid & 31;
    const int it = blockIdx.x & 1, ct = blockIdx.x >> 1;
    const int p = blockIdx.y;
    const int wm = wid >> 1, wn = wid & 1;
    const int i0 = it * 128, c0 = ct * 128;

    float d[2][8][4];
#pragma unroll
    for (int mi = 0; mi < 2; mi++)
#pragma unroll
        for (int nj = 0; nj < 8; nj++)
#pragma unroll
            for (int rg = 0; rg < 4; rg++) d[mi][nj][rg] = 0.0f;

    auto stage = [&](int c) {
        const unsigned stg = sbase + (unsigned)(c % 3) * STG_SZ;
        const int j0 = c * 64;
#pragma unroll
        for (int i = 0; i < 8; i++) {
            int idx = tid + 256 * i;
            int half = idx >> 10, r = (idx >> 3) & 127, seg = idx & 7;
            const __nv_bfloat16* src = (half ? g_attl : g_atth) + (size_t)(p * NN + i0 + r) * NN + j0 + seg * 8;
            cp16(stg + half * 16384 + r * 128 + ((seg ^ (r & 7)) << 4), src);
        }
#pragma unroll
        for (int i = 0; i < 8; i++) {
            int idx = tid + 256 * i;
            int half = idx >> 10, rem = idx & 1023;
            int r = rem >> 4, seg = rem & 15;
            const __nv_bfloat16* src = (half ? g_vl : g_vh) + (size_t)(p * NN + j0 + r) * CC + c0 + seg * 8;
            cp16(stg + 32768 + half * 16384 + r * 256 + ((seg ^ ((r & 7) << 1)) << 4), src);
        }
        cp_commit();
    };

    stage(0); stage(1);
    for (int c = 0; c < 4; c++) {
        if (c + 1 >= 4) cp_wait0(); else cp_wait1();
        __syncthreads();
        if (c + 2 < 4) stage(c + 2);
        const unsigned stg = sbase + (unsigned)(c % 3) * STG_SZ;
#pragma unroll
        for (int k16 = 0; k16 < 4; k16++) {
            unsigned a[2][2][4];
#pragma unroll
            for (int hf = 0; hf < 2; hf++)
#pragma unroll
                for (int mi = 0; mi < 2; mi++) {
                    int row = wm * 32 + mi * 16 + (l & 15);
                    ldsm4(a[hf][mi], stg + hf * 16384 + row * 128 +
                                     (((k16 * 2 + (l >> 4)) ^ (row & 7)) << 4));
                }
            unsigned b[2][8][2];
#pragma unroll
            for (int hf = 0; hf < 2; hf++)
#pragma unroll
                for (int cg = 0; cg < 4; cg++) {
                    int tileid = l >> 3;
                    int jr = (l & 7) + (tileid & 1) * 8;
                    int row = k16 * 16 + jr;
                    int seg = wn * 8 + cg * 2 + (tileid >> 1);
                    unsigned r4[4];
                    ldsm4t(r4, stg + 32768 + hf * 16384 + row * 256 +
                               ((seg ^ ((row & 7) << 1)) << 4));
                    b[hf][2 * cg][0] = r4[0]; b[hf][2 * cg][1] = r4[1];
                    b[hf][2 * cg + 1][0] = r4[2]; b[hf][2 * cg + 1][1] = r4[3];
                }
#pragma unroll
            for (int mi = 0; mi < 2; mi++)
#pragma unroll
                for (int nj = 0; nj < 8; nj++) {
                    mma16816(d[mi][nj], a[0][mi], b[0][nj]);
                    mma16816(d[mi][nj], a[0][mi], b[1][nj]);
                    mma16816(d[mi][nj], a[1][mi], b[0][nj]);
                }
        }
    }
    cp_wait0();
    __syncthreads();
    float* ep = (float*)dsm;
#pragma unroll
    for (int mi = 0; mi < 2; mi++)
#pragma unroll
        for (int nj = 0; nj < 8; nj++)
#pragma unroll
            for (int rg = 0; rg < 4; rg++) {
                int row = wm * 32 + mi * 16 + (l >> 2) + (rg >> 1) * 8;
                int col = wn * 64 + nj * 8 + (l & 3) * 2 + (rg & 1);
                ep[row * 129 + col] = d[mi][nj][rg];
            }
    __syncthreads();
    for (int r = wid; r < 128; r += 8) {
        float* dr = &g_virt[((size_t)p * NN + i0 + r) * CC + c0];
        for (int c = l; c < 128; c += 32) dr[c] = ep[r * 129 + c];
    }
}

__global__ __launch_bounds__(256) void stats_kernel()
{
    __shared__ float r1[256];
    __shared__ float r2[256];
    const int n = blockIdx.x, tid = threadIdx.x;
    float s = 0.0f, s2 = 0.0f;
    for (int e = tid; e < PP * CC; e += 256) {
        int p = e >> 9, c = e & 511;
        float v = g_virt[(p * NN + n) * CC + c];
        s += v; s2 += v * v;
    }
    r1[tid] = s; r2[tid] = s2;
    __syncthreads();
    for (int off = 128; off; off >>= 1) {
        if (tid < off) { r1[tid] += r1[tid + off]; r2[tid] += r2[tid + off]; }
        __syncthreads();
    }
    if (tid == 0) {
        const float invN = 1.0f / (float)(PP * CC);
        float mu = r1[0] * invN;
        float var = r2[0] * invN - mu * mu;
        g_mu[n] = mu;
        g_rs[n] = rsqrtf(var + 1e-5f);
    }
}

// ---------------- host ----------------
extern "C" void kernel_launch(void* const* d_in, const int* in_sizes, int n_in,
                              void* d_out, int out_size)
{
    const float* x     = (const float*)d_in[0];
    const int*   roi   = (const int*)d_in[1];
    const float* Wq    = (const float*)d_in[2];
    const float* Wk    = (const float*)d_in[3];
    const float* Wv    = (const float*)d_in[4];
    const float* Wc    = (const float*)d_in[5];
    const float* gamma = (const float*)d_in[6];
    const float* beta  = (const float*)d_in[7];
    float* out = (float*)d_out;

    cudaFuncSetAttribute(wino_v_kernel,     cudaFuncAttributeMaxDynamicSharedMemorySize, 198656);
    cudaFuncSetAttribute(wino_gemm_kernel,  cudaFuncAttributeMaxDynamicSharedMemorySize, 196608);
    cudaFuncSetAttribute(wino_inv_out_kernel, cudaFuncAttributeMaxDynamicSharedMemorySize, 131072);
    cudaFuncSetAttribute(scores_mma_kernel, cudaFuncAttributeMaxDynamicSharedMemorySize, 3 * STG_SZ);
    cudaFuncSetAttribute(virt_mma_kernel,   cudaFuncAttributeMaxDynamicSharedMemorySize, 3 * STG_SZ);

    wino_u_kernel<<<4096, 256>>>(Wq, Wk, Wv, Wc);
    wino_v_kernel<<<1024, 512, 198656>>>(0, x, gamma, beta);
    wino_gemm_kernel<<<dim3(64, 12, 16), 256, 196608>>>(0, 1536);
    wino_inv_qkv_kernel<<<16384, 512>>>();
    scores_mma_kernel<<<dim3(4, 256), 256, 3 * STG_SZ>>>();
    softmax_kernel<<<8192, 256>>>(roi);
    virt_mma_kernel<<<dim3(8, 256), 256, 3 * STG_SZ>>>();
    stats_kernel<<<256, 256>>>();
    wino_v_kernel<<<1024, 512, 198656>>>(1, x, gamma, beta);
    wino_gemm_kernel<<<dim3(64, 4, 16), 256, 196608>>>(1536, 512);
    wino_inv_out_kernel<<<1024, 512, 131072>>>(x, out);
}